// round 1
// baseline (speedup 1.0000x reference)
#include <cuda_runtime.h>
#include <math.h>

// ---------------- problem constants ----------------
#define BATCH   64
#define HDIM    56          // H = W = 56
#define CCH     256
#define NHEAD   8
#define HD      32          // head dim
#define WSZ     7
#define NWIN    49          // WSZ*WSZ
#define SHIFT   3
#define HIDDEN  1024
#define NWG     8           // windows per axis (56/7)
#define NW      64          // windows per image
#define BWIN    (BATCH*NW)          // 4096
#define TTOK    (BATCH*HDIM*HDIM)   // 200704 tokens
#define EPSLN   1e-5f

// ---------------- scratch (device globals; no allocation allowed) ----------------
__device__ float g_lnbuf [ (size_t)TTOK * CCH ];      // 205 MB  (ln1 windowed, later ln2)
__device__ float g_qkv   [ (size_t)TTOK * 3 * CCH ];  // 616 MB
__device__ float g_attn  [ (size_t)TTOK * CCH ];      // 205 MB
__device__ float g_hidden[ (size_t)TTOK * HIDDEN ];   // 822 MB

// ================= LayerNorm 1: gather (shift + window partition) + LN =================
// one block (256 thr) per windowed token; output row-major (TTOK x 256) in window order
__global__ __launch_bounds__(256) void ln1_kernel(const float* __restrict__ x,
                                                  const float* __restrict__ w,
                                                  const float* __restrict__ b)
{
    const int t   = blockIdx.x;
    const int tid = threadIdx.x;
    const int n   = t % NWIN;
    const int b_  = t / NWIN;
    const int r   = n / WSZ, c = n % WSZ;
    const int wi  = b_ & (NW - 1);
    const int bb  = b_ >> 6;
    const int wh  = wi >> 3, ww = wi & 7;
    const int h2  = (wh * WSZ + r + SHIFT) % HDIM;
    const int w2  = (ww * WSZ + c + SHIFT) % HDIM;
    const float* row = x + ((size_t)bb * (HDIM*HDIM) + h2 * HDIM + w2) * CCH;

    float v = row[tid];

    __shared__ float s1[256];
    __shared__ float s2[256];
    s1[tid] = v;  s2[tid] = v * v;
    __syncthreads();
    for (int s = 128; s > 0; s >>= 1) {
        if (tid < s) { s1[tid] += s1[tid + s]; s2[tid] += s2[tid + s]; }
        __syncthreads();
    }
    const float mean = s1[0] * (1.0f / CCH);
    const float var  = s2[0] * (1.0f / CCH) - mean * mean;
    const float inv  = rsqrtf(var + EPSLN);
    g_lnbuf[(size_t)t * CCH + tid] = (v - mean) * inv * w[tid] + b[tid];
}

// ================= LayerNorm 2: natural layout rows of d_out =================
__global__ __launch_bounds__(256) void ln2_kernel(const float* __restrict__ xin,
                                                  const float* __restrict__ w,
                                                  const float* __restrict__ b)
{
    const int t   = blockIdx.x;
    const int tid = threadIdx.x;
    float v = xin[(size_t)t * CCH + tid];

    __shared__ float s1[256];
    __shared__ float s2[256];
    s1[tid] = v;  s2[tid] = v * v;
    __syncthreads();
    for (int s = 128; s > 0; s >>= 1) {
        if (tid < s) { s1[tid] += s1[tid + s]; s2[tid] += s2[tid + s]; }
        __syncthreads();
    }
    const float mean = s1[0] * (1.0f / CCH);
    const float var  = s2[0] * (1.0f / CCH) - mean * mean;
    const float inv  = rsqrtf(var + EPSLN);
    g_lnbuf[(size_t)t * CCH + tid] = (v - mean) * inv * w[tid] + b[tid];
}

// ================= generic SGEMM: C = A (MxK, rm) * B^T (NxK, rm) + epilogue =================
// MODE 0: out = acc + bias                              (row-major out, ld = Nc)
// MODE 1: out = gelu(acc + bias)                        (exact erf)
// MODE 2: proj epilogue: window-reverse+unshift scatter + residual(x) -> out
// MODE 3: out = resid + acc + bias  (same index)
#define BM 128
#define BN 128
#define BKK 8
#define TM 8
#define TN 8

template <int MODE>
__global__ __launch_bounds__(256) void sgemm_kernel(const float* __restrict__ A,
                                                    const float* __restrict__ Bm,
                                                    const float* __restrict__ bias,
                                                    const float* __restrict__ resid,
                                                    float* __restrict__ out,
                                                    int M, int Nc, int K)
{
    __shared__ float As[BKK][BM];
    __shared__ float Bs[BKK][BN];

    const int tid = threadIdx.x;
    const int tx  = tid & 15;
    const int ty  = tid >> 4;
    const int rowA0 = blockIdx.y * BM;
    const int colB0 = blockIdx.x * BN;

    const int lrow = tid >> 1;            // 0..127
    const int lcol = (tid & 1) * 4;       // 0 or 4

    const float* Aptr = A  + (size_t)(rowA0 + lrow) * K + lcol;
    const float* Bptr = Bm + (size_t)(colB0 + lrow) * K + lcol;

    float acc[TM][TN];
#pragma unroll
    for (int i = 0; i < TM; i++)
#pragma unroll
        for (int j = 0; j < TN; j++) acc[i][j] = 0.0f;

    for (int k0 = 0; k0 < K; k0 += BKK) {
        float4 a4 = *(const float4*)(Aptr + k0);
        float4 b4 = *(const float4*)(Bptr + k0);
        As[lcol + 0][lrow] = a4.x; As[lcol + 1][lrow] = a4.y;
        As[lcol + 2][lrow] = a4.z; As[lcol + 3][lrow] = a4.w;
        Bs[lcol + 0][lrow] = b4.x; Bs[lcol + 1][lrow] = b4.y;
        Bs[lcol + 2][lrow] = b4.z; Bs[lcol + 3][lrow] = b4.w;
        __syncthreads();
#pragma unroll
        for (int kk = 0; kk < BKK; kk++) {
            float4 ra0 = *(const float4*)&As[kk][ty * TM];
            float4 ra1 = *(const float4*)&As[kk][ty * TM + 4];
            float4 rb0 = *(const float4*)&Bs[kk][tx * TN];
            float4 rb1 = *(const float4*)&Bs[kk][tx * TN + 4];
            float ra[TM] = {ra0.x, ra0.y, ra0.z, ra0.w, ra1.x, ra1.y, ra1.z, ra1.w};
            float rb[TN] = {rb0.x, rb0.y, rb0.z, rb0.w, rb1.x, rb1.y, rb1.z, rb1.w};
#pragma unroll
            for (int i = 0; i < TM; i++)
#pragma unroll
                for (int j = 0; j < TN; j++)
                    acc[i][j] = fmaf(ra[i], rb[j], acc[i][j]);
        }
        __syncthreads();
    }

    const int gr0 = rowA0 + ty * TM;
    const int gc0 = colB0 + tx * TN;

    if (MODE == 0 || MODE == 1) {
#pragma unroll
        for (int i = 0; i < TM; i++) {
            const size_t base = (size_t)(gr0 + i) * Nc + gc0;
#pragma unroll
            for (int j = 0; j < TN; j++) {
                float v = acc[i][j] + bias[gc0 + j];
                if (MODE == 1)
                    v = 0.5f * v * (1.0f + erff(v * 0.7071067811865475f));
                out[base + j] = v;
            }
        }
    } else if (MODE == 2) {
#pragma unroll
        for (int i = 0; i < TM; i++) {
            const int t  = gr0 + i;
            const int n  = t % NWIN;
            const int b_ = t / NWIN;
            const int r  = n / WSZ, c2 = n % WSZ;
            const int wi = b_ & (NW - 1);
            const int bb = b_ >> 6;
            const int wh = wi >> 3, ww = wi & 7;
            const int h2 = (wh * WSZ + r + SHIFT) % HDIM;
            const int w2 = (ww * WSZ + c2 + SHIFT) % HDIM;
            const size_t dbase = ((size_t)bb * (HDIM*HDIM) + h2 * HDIM + w2) * CCH;
#pragma unroll
            for (int j = 0; j < TN; j++) {
                const int col = gc0 + j;
                out[dbase + col] = acc[i][j] + bias[col] + resid[dbase + col];
            }
        }
    } else { // MODE 3
#pragma unroll
        for (int i = 0; i < TM; i++) {
            const size_t base = (size_t)(gr0 + i) * Nc + gc0;
#pragma unroll
            for (int j = 0; j < TN; j++)
                out[base + j] = resid[base + j] + acc[i][j] + bias[gc0 + j];
        }
    }
}

// ================= windowed attention: one block per (window, head) =================
__device__ __forceinline__ int grp_of(int h) { return (h < HDIM - WSZ) ? 0 : ((h < HDIM - SHIFT) ? 1 : 2); }

__global__ __launch_bounds__(256) void attn_kernel(const float* __restrict__ rpb)
{
    const int bh   = blockIdx.x;
    const int head = bh & (NHEAD - 1);
    const int b_   = bh >> 3;
    const int tid  = threadIdx.x;

    __shared__ float q[NWIN][HD];
    __shared__ float k[NWIN][HD];
    __shared__ float v[NWIN][HD];
    __shared__ float S[NWIN][52];

    const float scale = 0.17677669529663687f; // 1/sqrt(32)
    const size_t base = (size_t)b_ * NWIN * (3 * CCH) + head * HD;

    for (int idx = tid; idx < NWIN * HD; idx += 256) {
        const int i = idx >> 5, d = idx & 31;
        const size_t rb = base + (size_t)i * (3 * CCH);
        q[i][d] = g_qkv[rb + d] * scale;
        k[i][d] = g_qkv[rb + CCH + d];
        v[i][d] = g_qkv[rb + 2 * CCH + d];
    }
    __syncthreads();

    const int wi = b_ & (NW - 1);
    const int wh = wi >> 3, ww = wi & 7;

    for (int idx = tid; idx < NWIN * NWIN; idx += 256) {
        const int i = idx / NWIN, j = idx - NWIN * i;
        float s = 0.0f;
#pragma unroll
        for (int d = 0; d < HD; d++) s = fmaf(q[i][d], k[j][d], s);
        const int ri = i / WSZ, ci = i - WSZ * ri;
        const int rj = j / WSZ, cj = j - WSZ * rj;
        s += rpb[((ri - rj + WSZ - 1) * (2 * WSZ - 1) + (ci - cj + WSZ - 1)) * NHEAD + head];
        const int gi = grp_of(wh * WSZ + ri) * 3 + grp_of(ww * WSZ + ci);
        const int gj = grp_of(wh * WSZ + rj) * 3 + grp_of(ww * WSZ + cj);
        if (gi != gj) s -= 100.0f;
        S[i][j] = s;
    }
    __syncthreads();

    const int warp = tid >> 5, lane = tid & 31;
    for (int i = warp; i < NWIN; i += 8) {
        float v0 = (lane < NWIN) ? S[i][lane] : -1e30f;
        float v1 = (lane + 32 < NWIN) ? S[i][lane + 32] : -1e30f;
        float m = fmaxf(v0, v1);
#pragma unroll
        for (int off = 16; off > 0; off >>= 1) m = fmaxf(m, __shfl_xor_sync(0xffffffffu, m, off));
        float e0 = (lane < NWIN) ? __expf(v0 - m) : 0.0f;
        float e1 = (lane + 32 < NWIN) ? __expf(v1 - m) : 0.0f;
        float sum = e0 + e1;
#pragma unroll
        for (int off = 16; off > 0; off >>= 1) sum += __shfl_xor_sync(0xffffffffu, sum, off);
        const float inv = 1.0f / sum;
        if (lane < NWIN) S[i][lane] = e0 * inv;
        if (lane + 32 < NWIN) S[i][lane + 32] = e1 * inv;
    }
    __syncthreads();

    for (int idx = tid; idx < NWIN * HD; idx += 256) {
        const int i = idx >> 5, d = idx & 31;
        float s = 0.0f;
#pragma unroll
        for (int j = 0; j < NWIN; j++) s = fmaf(S[i][j], v[j][d], s);
        g_attn[((size_t)b_ * NWIN + i) * CCH + head * HD + d] = s;
    }
}

// ================= host launcher =================
extern "C" void kernel_launch(void* const* d_in, const int* in_sizes, int n_in,
                              void* d_out, int out_size)
{
    const float* x       = (const float*)d_in[0];
    const float* norm1_w = (const float*)d_in[1];
    const float* norm1_b = (const float*)d_in[2];
    const float* qkv_w   = (const float*)d_in[3];
    const float* qkv_b   = (const float*)d_in[4];
    const float* rpb     = (const float*)d_in[5];
    const float* proj_w  = (const float*)d_in[6];
    const float* proj_b  = (const float*)d_in[7];
    const float* norm2_w = (const float*)d_in[8];
    const float* norm2_b = (const float*)d_in[9];
    const float* fc1_w   = (const float*)d_in[10];
    const float* fc1_b   = (const float*)d_in[11];
    const float* fc2_w   = (const float*)d_in[12];
    const float* fc2_b   = (const float*)d_in[13];
    float* out = (float*)d_out;

    float *p_lnbuf, *p_qkv, *p_attn, *p_hidden;
    cudaGetSymbolAddress((void**)&p_lnbuf,  g_lnbuf);
    cudaGetSymbolAddress((void**)&p_qkv,    g_qkv);
    cudaGetSymbolAddress((void**)&p_attn,   g_attn);
    cudaGetSymbolAddress((void**)&p_hidden, g_hidden);

    const int Mb = TTOK / BM;  // 1568

    // 1. LN1 + shift + window partition
    ln1_kernel<<<TTOK, 256>>>(x, norm1_w, norm1_b);

    // 2. qkv = ln1 @ qkv_w^T + b   (200704 x 768)
    sgemm_kernel<0><<<dim3(3 * CCH / BN, Mb), 256>>>(p_lnbuf, qkv_w, qkv_b, nullptr,
                                                     p_qkv, TTOK, 3 * CCH, CCH);

    // 3. windowed attention
    attn_kernel<<<BWIN * NHEAD, 256>>>(rpb);

    // 4. proj + window-reverse + unshift + residual  ->  x1 in d_out
    sgemm_kernel<2><<<dim3(CCH / BN, Mb), 256>>>(p_attn, proj_w, proj_b, x,
                                                 out, TTOK, CCH, CCH);

    // 5. LN2
    ln2_kernel<<<TTOK, 256>>>(out, norm2_w, norm2_b);

    // 6. hidden = gelu(ln2 @ fc1^T + b)   (200704 x 1024)
    sgemm_kernel<1><<<dim3(HIDDEN / BN, Mb), 256>>>(p_lnbuf, fc1_w, fc1_b, nullptr,
                                                    p_hidden, TTOK, HIDDEN, CCH);

    // 7. out = x1 + hidden @ fc2^T + b
    sgemm_kernel<3><<<dim3(CCH / BN, Mb), 256>>>(p_hidden, fc2_w, fc2_b, out,
                                                 out, TTOK, CCH, HIDDEN);
}

// round 2
// speedup vs baseline: 1.8229x; 1.8229x over previous
#include <cuda_runtime.h>
#include <math.h>
#include <stdint.h>

// ---------------- problem constants ----------------
#define BATCH   64
#define HDIM    56
#define CCH     256
#define NHEAD   8
#define HD      32
#define WSZ     7
#define NWIN    49
#define SHIFT   3
#define HIDDEN  1024
#define NW      64
#define BWIN    (BATCH*NW)
#define TTOK    (BATCH*HDIM*HDIM)   // 200704
#define EPSLN   1e-5f

// ---------------- scratch ----------------
__device__ float g_lnbuf [ (size_t)TTOK * CCH ];
__device__ float g_qkv   [ (size_t)TTOK * 3 * CCH ];
__device__ float g_attn  [ (size_t)TTOK * CCH ];
__device__ float g_hidden[ (size_t)TTOK * HIDDEN ];

// ================= LN1: shift + window-partition gather + LN =================
__global__ __launch_bounds__(256) void ln1_kernel(const float* __restrict__ x,
                                                  const float* __restrict__ w,
                                                  const float* __restrict__ b)
{
    const int t   = blockIdx.x;
    const int tid = threadIdx.x;
    const int n   = t % NWIN;
    const int b_  = t / NWIN;
    const int r   = n / WSZ, c = n % WSZ;
    const int wi  = b_ & (NW - 1);
    const int bb  = b_ >> 6;
    const int wh  = wi >> 3, ww = wi & 7;
    const int h2  = (wh * WSZ + r + SHIFT) % HDIM;
    const int w2  = (ww * WSZ + c + SHIFT) % HDIM;
    const float* row = x + ((size_t)bb * (HDIM*HDIM) + h2 * HDIM + w2) * CCH;

    float v = row[tid];
    __shared__ float s1[256], s2[256];
    s1[tid] = v;  s2[tid] = v * v;
    __syncthreads();
    for (int s = 128; s > 0; s >>= 1) {
        if (tid < s) { s1[tid] += s1[tid + s]; s2[tid] += s2[tid + s]; }
        __syncthreads();
    }
    const float mean = s1[0] * (1.0f / CCH);
    const float var  = s2[0] * (1.0f / CCH) - mean * mean;
    const float inv  = rsqrtf(var + EPSLN);
    g_lnbuf[(size_t)t * CCH + tid] = (v - mean) * inv * w[tid] + b[tid];
}

// ================= LN2 =================
__global__ __launch_bounds__(256) void ln2_kernel(const float* __restrict__ xin,
                                                  const float* __restrict__ w,
                                                  const float* __restrict__ b)
{
    const int t   = blockIdx.x;
    const int tid = threadIdx.x;
    float v = xin[(size_t)t * CCH + tid];
    __shared__ float s1[256], s2[256];
    s1[tid] = v;  s2[tid] = v * v;
    __syncthreads();
    for (int s = 128; s > 0; s >>= 1) {
        if (tid < s) { s1[tid] += s1[tid + s]; s2[tid] += s2[tid + s]; }
        __syncthreads();
    }
    const float mean = s1[0] * (1.0f / CCH);
    const float var  = s2[0] * (1.0f / CCH) - mean * mean;
    const float inv  = rsqrtf(var + EPSLN);
    g_lnbuf[(size_t)t * CCH + tid] = (v - mean) * inv * w[tid] + b[tid];
}

// ================= TF32 tensor-core GEMM: C = A(MxK,rm) * B^T (B: NxK,rm) =================
// MODE 0: out = acc + bias
// MODE 1: out = gelu(acc + bias)
// MODE 2: window-reverse+unshift scatter + residual
// MODE 3: out = resid + acc + bias

__device__ __forceinline__ uint32_t f2tf32(float f) {
    uint32_t u;
    asm("cvt.rna.tf32.f32 %0, %1;" : "=r"(u) : "f"(f));
    return u;
}

__device__ __forceinline__ void mma_tf32(float c[4], const uint32_t a[4], const uint32_t b[2]) {
    asm volatile(
        "mma.sync.aligned.m16n8k8.row.col.f32.tf32.tf32.f32 "
        "{%0,%1,%2,%3},{%4,%5,%6,%7},{%8,%9},{%0,%1,%2,%3};\n"
        : "+f"(c[0]), "+f"(c[1]), "+f"(c[2]), "+f"(c[3])
        : "r"(a[0]), "r"(a[1]), "r"(a[2]), "r"(a[3]), "r"(b[0]), "r"(b[1]));
}

#define GPITCH 20   // smem row pitch in words: float4-aligned AND conflict-free frag loads

template <int MODE>
__global__ __launch_bounds__(256) void tc_gemm_kernel(const float* __restrict__ A,
                                                      const float* __restrict__ Bm,
                                                      const float* __restrict__ bias,
                                                      const float* __restrict__ resid,
                                                      float* __restrict__ out,
                                                      int M, int Nc, int K)
{
    __shared__ uint32_t As[128 * GPITCH];
    __shared__ uint32_t Bs[128 * GPITCH];

    const int tid  = threadIdx.x;
    const int warp = tid >> 5;
    const int lane = tid & 31;
    const int g    = lane >> 2;   // groupID
    const int tig  = lane & 3;    // thread-in-group
    const int wm   = warp >> 2;   // 0..1
    const int wn   = warp & 3;    // 0..3

    const int rowA0 = blockIdx.y * 128;
    const int colB0 = blockIdx.x * 128;

    // global load mapping: 128 rows x 16 cols per chunk; thread -> (row tid>>2 [+64], 4 cols)
    const int lr = tid >> 2;
    const int lc = (tid & 3) * 4;
    const float* Ag  = A  + (size_t)(rowA0 + lr) * K + lc;
    const float* Ag2 = Ag + (size_t)64 * K;
    const float* Bg  = Bm + (size_t)(colB0 + lr) * K + lc;
    const float* Bg2 = Bg + (size_t)64 * K;

    float acc[4][4][4];
#pragma unroll
    for (int mi = 0; mi < 4; mi++)
#pragma unroll
        for (int ni = 0; ni < 4; ni++)
#pragma unroll
            for (int r = 0; r < 4; r++) acc[mi][ni][r] = 0.0f;

    // prefetch chunk 0
    float4 ra  = *(const float4*)(Ag);
    float4 ra2 = *(const float4*)(Ag2);
    float4 rb  = *(const float4*)(Bg);
    float4 rb2 = *(const float4*)(Bg2);

    for (int k0 = 0; k0 < K; k0 += 16) {
        // store current chunk (converted to tf32 bits)
        uint32_t* pa  = &As[lr * GPITCH + lc];
        uint32_t* pa2 = &As[(lr + 64) * GPITCH + lc];
        uint32_t* pb  = &Bs[lr * GPITCH + lc];
        uint32_t* pb2 = &Bs[(lr + 64) * GPITCH + lc];
        pa[0]  = f2tf32(ra.x);  pa[1]  = f2tf32(ra.y);  pa[2]  = f2tf32(ra.z);  pa[3]  = f2tf32(ra.w);
        pa2[0] = f2tf32(ra2.x); pa2[1] = f2tf32(ra2.y); pa2[2] = f2tf32(ra2.z); pa2[3] = f2tf32(ra2.w);
        pb[0]  = f2tf32(rb.x);  pb[1]  = f2tf32(rb.y);  pb[2]  = f2tf32(rb.z);  pb[3]  = f2tf32(rb.w);
        pb2[0] = f2tf32(rb2.x); pb2[1] = f2tf32(rb2.y); pb2[2] = f2tf32(rb2.z); pb2[3] = f2tf32(rb2.w);
        __syncthreads();

        // prefetch next chunk (overlaps with MMA below)
        if (k0 + 16 < K) {
            ra  = *(const float4*)(Ag  + k0 + 16);
            ra2 = *(const float4*)(Ag2 + k0 + 16);
            rb  = *(const float4*)(Bg  + k0 + 16);
            rb2 = *(const float4*)(Bg2 + k0 + 16);
        }

#pragma unroll
        for (int kk = 0; kk < 16; kk += 8) {
            uint32_t afr[4][4];
#pragma unroll
            for (int mi = 0; mi < 4; mi++) {
                const int r0 = wm * 64 + mi * 16 + g;
                afr[mi][0] = As[r0 * GPITCH + kk + tig];
                afr[mi][1] = As[(r0 + 8) * GPITCH + kk + tig];
                afr[mi][2] = As[r0 * GPITCH + kk + tig + 4];
                afr[mi][3] = As[(r0 + 8) * GPITCH + kk + tig + 4];
            }
            uint32_t bfr[4][2];
#pragma unroll
            for (int ni = 0; ni < 4; ni++) {
                const int nb = wn * 32 + ni * 8 + g;
                bfr[ni][0] = Bs[nb * GPITCH + kk + tig];
                bfr[ni][1] = Bs[nb * GPITCH + kk + tig + 4];
            }
#pragma unroll
            for (int mi = 0; mi < 4; mi++)
#pragma unroll
                for (int ni = 0; ni < 4; ni++)
                    mma_tf32(acc[mi][ni], afr[mi], bfr[ni]);
        }
        __syncthreads();
    }

    // ---------------- epilogue ----------------
#pragma unroll
    for (int mi = 0; mi < 4; mi++) {
        const int r0 = rowA0 + wm * 64 + mi * 16 + g;
        const int r1 = r0 + 8;

        size_t ob0, ob1;   // output row bases
        if (MODE == 2) {
            // window-reverse + unshift scatter indices
            int rr[2] = {r0, r1};
            size_t db[2];
#pragma unroll
            for (int q = 0; q < 2; q++) {
                const int t  = rr[q];
                const int n  = t % NWIN;
                const int b_ = t / NWIN;
                const int r  = n / WSZ, c2 = n % WSZ;
                const int wi = b_ & (NW - 1);
                const int bb = b_ >> 6;
                const int wh = wi >> 3, ww = wi & 7;
                const int h2 = (wh * WSZ + r + SHIFT) % HDIM;
                const int w2 = (ww * WSZ + c2 + SHIFT) % HDIM;
                db[q] = ((size_t)bb * (HDIM*HDIM) + h2 * HDIM + w2) * CCH;
            }
            ob0 = db[0]; ob1 = db[1];
        } else {
            ob0 = (size_t)r0 * Nc;
            ob1 = (size_t)r1 * Nc;
        }

#pragma unroll
        for (int ni = 0; ni < 4; ni++) {
            const int col = colB0 + wn * 32 + ni * 8 + 2 * tig;
            const float b0 = bias[col], b1 = bias[col + 1];
            float v00 = acc[mi][ni][0] + b0;
            float v01 = acc[mi][ni][1] + b1;
            float v10 = acc[mi][ni][2] + b0;
            float v11 = acc[mi][ni][3] + b1;
            if (MODE == 1) {
                v00 = 0.5f * v00 * (1.0f + erff(v00 * 0.7071067811865475f));
                v01 = 0.5f * v01 * (1.0f + erff(v01 * 0.7071067811865475f));
                v10 = 0.5f * v10 * (1.0f + erff(v10 * 0.7071067811865475f));
                v11 = 0.5f * v11 * (1.0f + erff(v11 * 0.7071067811865475f));
            }
            if (MODE == 2 || MODE == 3) {
                v00 += resid[ob0 + col];     v01 += resid[ob0 + col + 1];
                v10 += resid[ob1 + col];     v11 += resid[ob1 + col + 1];
            }
            *(float2*)(out + ob0 + col) = make_float2(v00, v01);
            *(float2*)(out + ob1 + col) = make_float2(v10, v11);
        }
    }
}

// ================= windowed attention =================
__device__ __forceinline__ int grp_of(int h) { return (h < HDIM - WSZ) ? 0 : ((h < HDIM - SHIFT) ? 1 : 2); }

__global__ __launch_bounds__(256) void attn_kernel(const float* __restrict__ rpb)
{
    const int bh   = blockIdx.x;
    const int head = bh & (NHEAD - 1);
    const int b_   = bh >> 3;
    const int tid  = threadIdx.x;

    __shared__ float q[NWIN][HD];
    __shared__ float k[NWIN][HD];
    __shared__ float v[NWIN][HD];
    __shared__ float S[NWIN][52];

    const float scale = 0.17677669529663687f;
    const size_t base = (size_t)b_ * NWIN * (3 * CCH) + head * HD;

    for (int idx = tid; idx < NWIN * HD; idx += 256) {
        const int i = idx >> 5, d = idx & 31;
        const size_t rb = base + (size_t)i * (3 * CCH);
        q[i][d] = g_qkv[rb + d] * scale;
        k[i][d] = g_qkv[rb + CCH + d];
        v[i][d] = g_qkv[rb + 2 * CCH + d];
    }
    __syncthreads();

    const int wi = b_ & (NW - 1);
    const int wh = wi >> 3, ww = wi & 7;

    for (int idx = tid; idx < NWIN * NWIN; idx += 256) {
        const int i = idx / NWIN, j = idx - NWIN * i;
        float s = 0.0f;
#pragma unroll
        for (int d = 0; d < HD; d++) s = fmaf(q[i][d], k[j][d], s);
        const int ri = i / WSZ, ci = i - WSZ * ri;
        const int rj = j / WSZ, cj = j - WSZ * rj;
        s += rpb[((ri - rj + WSZ - 1) * (2 * WSZ - 1) + (ci - cj + WSZ - 1)) * NHEAD + head];
        const int gi = grp_of(wh * WSZ + ri) * 3 + grp_of(ww * WSZ + ci);
        const int gj = grp_of(wh * WSZ + rj) * 3 + grp_of(ww * WSZ + cj);
        if (gi != gj) s -= 100.0f;
        S[i][j] = s;
    }
    __syncthreads();

    const int warp = tid >> 5, lane = tid & 31;
    for (int i = warp; i < NWIN; i += 8) {
        float v0 = (lane < NWIN) ? S[i][lane] : -1e30f;
        float v1 = (lane + 32 < NWIN) ? S[i][lane + 32] : -1e30f;
        float m = fmaxf(v0, v1);
#pragma unroll
        for (int off = 16; off > 0; off >>= 1) m = fmaxf(m, __shfl_xor_sync(0xffffffffu, m, off));
        float e0 = (lane < NWIN) ? __expf(v0 - m) : 0.0f;
        float e1 = (lane + 32 < NWIN) ? __expf(v1 - m) : 0.0f;
        float sum = e0 + e1;
#pragma unroll
        for (int off = 16; off > 0; off >>= 1) sum += __shfl_xor_sync(0xffffffffu, sum, off);
        const float inv = 1.0f / sum;
        if (lane < NWIN) S[i][lane] = e0 * inv;
        if (lane + 32 < NWIN) S[i][lane + 32] = e1 * inv;
    }
    __syncthreads();

    for (int idx = tid; idx < NWIN * HD; idx += 256) {
        const int i = idx >> 5, d = idx & 31;
        float s = 0.0f;
#pragma unroll
        for (int j = 0; j < NWIN; j++) s = fmaf(S[i][j], v[j][d], s);
        g_attn[((size_t)b_ * NWIN + i) * CCH + head * HD + d] = s;
    }
}

// ================= host launcher =================
extern "C" void kernel_launch(void* const* d_in, const int* in_sizes, int n_in,
                              void* d_out, int out_size)
{
    const float* x       = (const float*)d_in[0];
    const float* norm1_w = (const float*)d_in[1];
    const float* norm1_b = (const float*)d_in[2];
    const float* qkv_w   = (const float*)d_in[3];
    const float* qkv_b   = (const float*)d_in[4];
    const float* rpb     = (const float*)d_in[5];
    const float* proj_w  = (const float*)d_in[6];
    const float* proj_b  = (const float*)d_in[7];
    const float* norm2_w = (const float*)d_in[8];
    const float* norm2_b = (const float*)d_in[9];
    const float* fc1_w   = (const float*)d_in[10];
    const float* fc1_b   = (const float*)d_in[11];
    const float* fc2_w   = (const float*)d_in[12];
    const float* fc2_b   = (const float*)d_in[13];
    float* out = (float*)d_out;

    float *p_lnbuf, *p_qkv, *p_attn, *p_hidden;
    cudaGetSymbolAddress((void**)&p_lnbuf,  g_lnbuf);
    cudaGetSymbolAddress((void**)&p_qkv,    g_qkv);
    cudaGetSymbolAddress((void**)&p_attn,   g_attn);
    cudaGetSymbolAddress((void**)&p_hidden, g_hidden);

    const int Mb = TTOK / 128;  // 1568

    ln1_kernel<<<TTOK, 256>>>(x, norm1_w, norm1_b);

    tc_gemm_kernel<0><<<dim3(3 * CCH / 128, Mb), 256>>>(p_lnbuf, qkv_w, qkv_b, nullptr,
                                                        p_qkv, TTOK, 3 * CCH, CCH);

    attn_kernel<<<BWIN * NHEAD, 256>>>(rpb);

    tc_gemm_kernel<2><<<dim3(CCH / 128, Mb), 256>>>(p_attn, proj_w, proj_b, x,
                                                    out, TTOK, CCH, CCH);

    ln2_kernel<<<TTOK, 256>>>(out, norm2_w, norm2_b);

    tc_gemm_kernel<1><<<dim3(HIDDEN / 128, Mb), 256>>>(p_lnbuf, fc1_w, fc1_b, nullptr,
                                                       p_hidden, TTOK, HIDDEN, CCH);

    tc_gemm_kernel<3><<<dim3(CCH / 128, Mb), 256>>>(p_hidden, fc2_w, fc2_b, out,
                                                    out, TTOK, CCH, HIDDEN);
}

// round 5
// speedup vs baseline: 2.3666x; 1.2982x over previous
#include <cuda_runtime.h>
#include <cuda_bf16.h>
#include <math.h>
#include <stdint.h>

// ---------------- problem constants ----------------
#define BATCH   64
#define HDIM    56
#define CCH     256
#define NHEAD   8
#define HD      32
#define WSZ     7
#define NWIN    49
#define SHIFT   3
#define HIDDEN  1024
#define NW      64
#define BWIN    (BATCH*NW)
#define TTOK    (BATCH*HDIM*HDIM)   // 200704
#define EPSLN   1e-5f

typedef __nv_bfloat16 bf16;

// ---------------- scratch (bf16 activations) ----------------
__device__ bf16  g_lnbuf [ (size_t)TTOK * CCH ];
__device__ bf16  g_qkv   [ (size_t)TTOK * 3 * CCH ];
__device__ bf16  g_attn  [ (size_t)TTOK * CCH ];
__device__ bf16  g_hidden[ (size_t)TTOK * HIDDEN ];
__device__ bf16  g_wt    [ 786432 ];   // qkv_w | proj_w | fc1_w | fc2_w (bf16)

#define OFF_QKV  0
#define OFF_PROJ 196608
#define OFF_FC1  262144
#define OFF_FC2  524288

// ================= fp32 -> bf16 weight convert =================
__global__ __launch_bounds__(256) void cvt_kernel(const float* __restrict__ src,
                                                  bf16* __restrict__ dst)
{
    const int i = (blockIdx.x * 256 + threadIdx.x) * 4;
    float4 v = *(const float4*)(src + i);
    bf16 o[4] = {__float2bfloat16_rn(v.x), __float2bfloat16_rn(v.y),
                 __float2bfloat16_rn(v.z), __float2bfloat16_rn(v.w)};
    *(uint2*)(dst + i) = *(const uint2*)o;
}

// ================= LayerNorm (GATHER=1 fuses shift + window partition) =================
template <int GATHER>
__global__ __launch_bounds__(256) void ln_kernel(const float* __restrict__ x,
                                                 const float* __restrict__ w,
                                                 const float* __restrict__ b)
{
    const int t   = blockIdx.x;
    const int tid = threadIdx.x;

    const float* row;
    if (GATHER) {
        const int n   = t % NWIN;
        const int b_  = t / NWIN;
        const int r   = n / WSZ, c = n % WSZ;
        const int wi  = b_ & (NW - 1);
        const int bb  = b_ >> 6;
        const int wh  = wi >> 3, ww = wi & 7;
        const int h2  = (wh * WSZ + r + SHIFT) % HDIM;
        const int w2  = (ww * WSZ + c + SHIFT) % HDIM;
        row = x + ((size_t)bb * (HDIM*HDIM) + h2 * HDIM + w2) * CCH;
    } else {
        row = x + (size_t)t * CCH;
    }

    float v = row[tid];
    __shared__ float s1[256], s2[256];
    s1[tid] = v;  s2[tid] = v * v;
    __syncthreads();
    for (int s = 128; s > 0; s >>= 1) {
        if (tid < s) { s1[tid] += s1[tid + s]; s2[tid] += s2[tid + s]; }
        __syncthreads();
    }
    const float mean = s1[0] * (1.0f / CCH);
    const float var  = s2[0] * (1.0f / CCH) - mean * mean;
    const float inv  = rsqrtf(var + EPSLN);
    g_lnbuf[(size_t)t * CCH + tid] = __float2bfloat16_rn((v - mean) * inv * w[tid] + b[tid]);
}

// ================= bf16 tensor-core GEMM: C = A(MxK,rm) * B^T (B: NxK,rm) =================
// MODE 0: out(bf16) = acc + bias
// MODE 1: out(bf16) = gelu(acc + bias)
// MODE 2: out(f32)  = window-reverse scatter: acc + bias + resid
// MODE 3: out(f32)  = acc + bias + resid

#define BKC   32
#define PITCH 40
#define STG_ELEMS (128 * PITCH)

__device__ __forceinline__ void mma_bf16(float c[4], const uint32_t a[4], const uint32_t b[2]) {
    asm volatile(
        "mma.sync.aligned.m16n8k16.row.col.f32.bf16.bf16.f32 "
        "{%0,%1,%2,%3},{%4,%5,%6,%7},{%8,%9},{%0,%1,%2,%3};\n"
        : "+f"(c[0]), "+f"(c[1]), "+f"(c[2]), "+f"(c[3])
        : "r"(a[0]), "r"(a[1]), "r"(a[2]), "r"(a[3]), "r"(b[0]), "r"(b[1]));
}

#define LDSM4(r0,r1,r2,r3,addr) \
    asm volatile("ldmatrix.sync.aligned.m8n8.x4.shared.b16 {%0,%1,%2,%3}, [%4];" \
                 : "=r"(r0), "=r"(r1), "=r"(r2), "=r"(r3) : "r"(addr))

#define CPASYNC16(smem_u32, gptr) \
    asm volatile("cp.async.cg.shared.global [%0], [%1], 16;" :: "r"(smem_u32), "l"(gptr))

template <int MODE>
__global__ __launch_bounds__(256, 2) void tc_gemm_kernel(const bf16* __restrict__ A,
                                                         const bf16* __restrict__ Bm,
                                                         const float* __restrict__ bias,
                                                         const float* __restrict__ resid,
                                                         void* __restrict__ outv,
                                                         int Nc, int K)
{
    __shared__ bf16 As[2][STG_ELEMS];
    __shared__ bf16 Bs[2][STG_ELEMS];

    const int tid  = threadIdx.x;
    const int warp = tid >> 5;
    const int lane = tid & 31;
    const int g    = lane >> 2;
    const int tig  = lane & 3;
    const int wm   = warp >> 2;
    const int wn   = warp & 3;

    const int rowA0 = blockIdx.y * 128;
    const int colB0 = blockIdx.x * 128;

    const int ldr = tid >> 1;
    const int ldk = (tid & 1) * 16;
    const bf16* Ag = A  + (size_t)(rowA0 + ldr) * K + ldk;
    const bf16* Bg = Bm + (size_t)(colB0 + ldr) * K + ldk;
    const uint32_t sA = (uint32_t)__cvta_generic_to_shared(&As[0][ldr * PITCH + ldk]);
    const uint32_t sB = (uint32_t)__cvta_generic_to_shared(&Bs[0][ldr * PITCH + ldk]);
    const uint32_t stgB = STG_ELEMS * 2;

    const uint32_t aBase = (uint32_t)__cvta_generic_to_shared(
        &As[0][(wm * 64 + (lane & 15)) * PITCH + (lane >> 4) * 8]);
    const uint32_t bBase = (uint32_t)__cvta_generic_to_shared(
        &Bs[0][(wn * 32 + (lane & 7) + ((lane >> 4) & 1) * 8) * PITCH + ((lane >> 3) & 1) * 8]);

    float acc[4][4][4];
#pragma unroll
    for (int mi = 0; mi < 4; mi++)
#pragma unroll
        for (int ni = 0; ni < 4; ni++)
#pragma unroll
            for (int r = 0; r < 4; r++) acc[mi][ni][r] = 0.0f;

    const int nch = K / BKC;

    CPASYNC16(sA,      Ag);
    CPASYNC16(sA + 16, Ag + 8);
    CPASYNC16(sB,      Bg);
    CPASYNC16(sB + 16, Bg + 8);
    asm volatile("cp.async.commit_group;");

    for (int c = 0; c < nch; c++) {
        const int cur = c & 1;
        if (c + 1 < nch) {
            const int nxt = cur ^ 1;
            const int ko = (c + 1) * BKC;
            CPASYNC16(sA + nxt * stgB,      Ag + ko);
            CPASYNC16(sA + nxt * stgB + 16, Ag + ko + 8);
            CPASYNC16(sB + nxt * stgB,      Bg + ko);
            CPASYNC16(sB + nxt * stgB + 16, Bg + ko + 8);
            asm volatile("cp.async.commit_group;");
            asm volatile("cp.async.wait_group 1;");
        } else {
            asm volatile("cp.async.wait_group 0;");
        }
        __syncthreads();

        const uint32_t aS = aBase + cur * stgB;
        const uint32_t bS = bBase + cur * stgB;
#pragma unroll
        for (int kk = 0; kk < 2; kk++) {
            uint32_t afr[4][4];
#pragma unroll
            for (int mi = 0; mi < 4; mi++)
                LDSM4(afr[mi][0], afr[mi][1], afr[mi][2], afr[mi][3],
                      aS + (mi * 16 * PITCH + kk * 16) * 2);
            uint32_t bfr[4][2];
#pragma unroll
            for (int ni2 = 0; ni2 < 2; ni2++)
                LDSM4(bfr[ni2 * 2][0], bfr[ni2 * 2][1], bfr[ni2 * 2 + 1][0], bfr[ni2 * 2 + 1][1],
                      bS + (ni2 * 16 * PITCH + kk * 16) * 2);
#pragma unroll
            for (int mi = 0; mi < 4; mi++)
#pragma unroll
                for (int ni = 0; ni < 4; ni++)
                    mma_bf16(acc[mi][ni], afr[mi], bfr[ni]);
        }
        __syncthreads();
    }

    // ---------------- epilogue ----------------
#pragma unroll
    for (int mi = 0; mi < 4; mi++) {
        const int r0 = rowA0 + wm * 64 + mi * 16 + g;
        const int r1 = r0 + 8;

        size_t ob0, ob1;
        if (MODE == 2) {
            int rr[2] = {r0, r1};
            size_t db[2];
#pragma unroll
            for (int q = 0; q < 2; q++) {
                const int t  = rr[q];
                const int n  = t % NWIN;
                const int b_ = t / NWIN;
                const int r  = n / WSZ, c2 = n % WSZ;
                const int wi = b_ & (NW - 1);
                const int bb = b_ >> 6;
                const int wh = wi >> 3, ww = wi & 7;
                const int h2 = (wh * WSZ + r + SHIFT) % HDIM;
                const int w2 = (ww * WSZ + c2 + SHIFT) % HDIM;
                db[q] = ((size_t)bb * (HDIM*HDIM) + h2 * HDIM + w2) * CCH;
            }
            ob0 = db[0]; ob1 = db[1];
        } else {
            ob0 = (size_t)r0 * Nc;
            ob1 = (size_t)r1 * Nc;
        }

#pragma unroll
        for (int ni = 0; ni < 4; ni++) {
            const int col = colB0 + wn * 32 + ni * 8 + 2 * tig;
            const float b0 = bias[col], b1 = bias[col + 1];
            float v00 = acc[mi][ni][0] + b0;
            float v01 = acc[mi][ni][1] + b1;
            float v10 = acc[mi][ni][2] + b0;
            float v11 = acc[mi][ni][3] + b1;
            if (MODE == 1) {
                v00 = 0.5f * v00 * (1.0f + erff(v00 * 0.7071067811865475f));
                v01 = 0.5f * v01 * (1.0f + erff(v01 * 0.7071067811865475f));
                v10 = 0.5f * v10 * (1.0f + erff(v10 * 0.7071067811865475f));
                v11 = 0.5f * v11 * (1.0f + erff(v11 * 0.7071067811865475f));
            }
            if (MODE == 0 || MODE == 1) {
                bf16* out = (bf16*)outv;
                bf16 p0[2] = {__float2bfloat16_rn(v00), __float2bfloat16_rn(v01)};
                bf16 p1[2] = {__float2bfloat16_rn(v10), __float2bfloat16_rn(v11)};
                *(uint32_t*)(out + ob0 + col) = *(const uint32_t*)p0;
                *(uint32_t*)(out + ob1 + col) = *(const uint32_t*)p1;
            } else {
                float* out = (float*)outv;
                v00 += resid[ob0 + col];  v01 += resid[ob0 + col + 1];
                v10 += resid[ob1 + col];  v11 += resid[ob1 + col + 1];
                *(float2*)(out + ob0 + col) = make_float2(v00, v01);
                *(float2*)(out + ob1 + col) = make_float2(v10, v11);
            }
        }
    }
}

// ================= windowed attention (bf16 I/O, fp32 compute) =================
__device__ __forceinline__ int grp_of(int h) { return (h < HDIM - WSZ) ? 0 : ((h < HDIM - SHIFT) ? 1 : 2); }

__global__ __launch_bounds__(256) void attn_kernel(const float* __restrict__ rpb)
{
    const int bh   = blockIdx.x;
    const int head = bh & (NHEAD - 1);
    const int b_   = bh >> 3;
    const int tid  = threadIdx.x;

    __shared__ float q[NWIN][HD];
    __shared__ float k[NWIN][HD];
    __shared__ float v[NWIN][HD];
    __shared__ float S[NWIN][52];

    const float scale = 0.17677669529663687f;
    const size_t base = (size_t)b_ * NWIN * (3 * CCH) + head * HD;

    for (int idx = tid; idx < NWIN * HD; idx += 256) {
        const int i = idx >> 5, d = idx & 31;
        const size_t rb = base + (size_t)i * (3 * CCH);
        q[i][d] = __bfloat162float(g_qkv[rb + d]) * scale;
        k[i][d] = __bfloat162float(g_qkv[rb + CCH + d]);
        v[i][d] = __bfloat162float(g_qkv[rb + 2 * CCH + d]);
    }
    __syncthreads();

    const int wi = b_ & (NW - 1);
    const int wh = wi >> 3, ww = wi & 7;

    for (int idx = tid; idx < NWIN * NWIN; idx += 256) {
        const int i = idx / NWIN, j = idx - NWIN * i;
        float s = 0.0f;
#pragma unroll
        for (int d = 0; d < HD; d++) s = fmaf(q[i][d], k[j][d], s);
        const int ri = i / WSZ, ci = i - WSZ * ri;
        const int rj = j / WSZ, cj = j - WSZ * rj;
        s += rpb[((ri - rj + WSZ - 1) * (2 * WSZ - 1) + (ci - cj + WSZ - 1)) * NHEAD + head];
        const int gi = grp_of(wh * WSZ + ri) * 3 + grp_of(ww * WSZ + ci);
        const int gj = grp_of(wh * WSZ + rj) * 3 + grp_of(ww * WSZ + cj);
        if (gi != gj) s -= 100.0f;
        S[i][j] = s;
    }
    __syncthreads();

    const int warp = tid >> 5, lane = tid & 31;
    for (int i = warp; i < NWIN; i += 8) {
        float v0 = (lane < NWIN) ? S[i][lane] : -1e30f;
        float v1 = (lane + 32 < NWIN) ? S[i][lane + 32] : -1e30f;
        float m = fmaxf(v0, v1);
#pragma unroll
        for (int off = 16; off > 0; off >>= 1) m = fmaxf(m, __shfl_xor_sync(0xffffffffu, m, off));
        float e0 = (lane < NWIN) ? __expf(v0 - m) : 0.0f;
        float e1 = (lane + 32 < NWIN) ? __expf(v1 - m) : 0.0f;
        float sum = e0 + e1;
#pragma unroll
        for (int off = 16; off > 0; off >>= 1) sum += __shfl_xor_sync(0xffffffffu, sum, off);
        const float inv = 1.0f / sum;
        if (lane < NWIN) S[i][lane] = e0 * inv;
        if (lane + 32 < NWIN) S[i][lane + 32] = e1 * inv;
    }
    __syncthreads();

    for (int idx = tid; idx < NWIN * HD; idx += 256) {
        const int i = idx >> 5, d = idx & 31;
        float s = 0.0f;
#pragma unroll
        for (int j = 0; j < NWIN; j++) s = fmaf(S[i][j], v[j][d], s);
        g_attn[((size_t)b_ * NWIN + i) * CCH + head * HD + d] = __float2bfloat16_rn(s);
    }
}

// ================= host launcher =================
extern "C" void kernel_launch(void* const* d_in, const int* in_sizes, int n_in,
                              void* d_out, int out_size)
{
    const float* x       = (const float*)d_in[0];
    const float* norm1_w = (const float*)d_in[1];
    const float* norm1_b = (const float*)d_in[2];
    const float* qkv_w   = (const float*)d_in[3];
    const float* qkv_b   = (const float*)d_in[4];
    const float* rpb     = (const float*)d_in[5];
    const float* proj_w  = (const float*)d_in[6];
    const float* proj_b  = (const float*)d_in[7];
    const float* norm2_w = (const float*)d_in[8];
    const float* norm2_b = (const float*)d_in[9];
    const float* fc1_w   = (const float*)d_in[10];
    const float* fc1_b   = (const float*)d_in[11];
    const float* fc2_w   = (const float*)d_in[12];
    const float* fc2_b   = (const float*)d_in[13];
    float* out = (float*)d_out;

    bf16 *p_lnbuf, *p_qkv, *p_attn, *p_hidden, *p_wt;
    cudaGetSymbolAddress((void**)&p_lnbuf,  g_lnbuf);
    cudaGetSymbolAddress((void**)&p_qkv,    g_qkv);
    cudaGetSymbolAddress((void**)&p_attn,   g_attn);
    cudaGetSymbolAddress((void**)&p_hidden, g_hidden);
    cudaGetSymbolAddress((void**)&p_wt,     g_wt);

    const int Mb = TTOK / 128;  // 1568

    cvt_kernel<<<196608 / 1024, 256>>>(qkv_w,  p_wt + OFF_QKV);
    cvt_kernel<<< 65536 / 1024, 256>>>(proj_w, p_wt + OFF_PROJ);
    cvt_kernel<<<262144 / 1024, 256>>>(fc1_w,  p_wt + OFF_FC1);
    cvt_kernel<<<262144 / 1024, 256>>>(fc2_w,  p_wt + OFF_FC2);

    ln_kernel<1><<<TTOK, 256>>>(x, norm1_w, norm1_b);

    tc_gemm_kernel<0><<<dim3(3 * CCH / 128, Mb), 256>>>(p_lnbuf, p_wt + OFF_QKV, qkv_b,
                                                        nullptr, p_qkv, 3 * CCH, CCH);

    attn_kernel<<<BWIN * NHEAD, 256>>>(rpb);

    tc_gemm_kernel<2><<<dim3(CCH / 128, Mb), 256>>>(p_attn, p_wt + OFF_PROJ, proj_b,
                                                    x, out, CCH, CCH);

    ln_kernel<0><<<TTOK, 256>>>(out, norm2_w, norm2_b);

    tc_gemm_kernel<1><<<dim3(HIDDEN / 128, Mb), 256>>>(p_lnbuf, p_wt + OFF_FC1, fc1_b,
                                                       nullptr, p_hidden, HIDDEN, CCH);

    tc_gemm_kernel<3><<<dim3(CCH / 128, Mb), 256>>>(p_hidden, p_wt + OFF_FC2, fc2_b,
                                                    out, out, CCH, HIDDEN);
}